// round 5
// baseline (speedup 1.0000x reference)
#include <cuda_runtime.h>
#include <cuda_fp16.h>
#include <cstdint>

#define BATCH 8
#define NDIM  16384
#define CDIM  512

// fp16 hi/lo split operands, precomputed
__device__ __half g_Xt_h[(size_t)BATCH * CDIM * NDIM];  // [b][c][n]
__device__ __half g_Xt_l[(size_t)BATCH * CDIM * NDIM];
__device__ __half g_Xc_h[(size_t)BATCH * NDIM * CDIM];  // [b][n][c]
__device__ __half g_Xc_l[(size_t)BATCH * NDIM * CDIM];
__device__ __half g_M_h[(size_t)BATCH * CDIM * CDIM];   // [b][i][k]
__device__ __half g_M_l[(size_t)BATCH * CDIM * CDIM];
__device__ float  g_energy[(size_t)BATCH * CDIM * CDIM];

// ---- helpers -------------------------------------------------------------
__device__ __forceinline__ uint32_t s2u(const void* p) {
    uint32_t a;
    asm("{ .reg .u64 t; cvta.to.shared.u64 t, %1; cvt.u32.u64 %0, t; }" : "=r"(a) : "l"(p));
    return a;
}
__device__ __forceinline__ void ldm4(uint32_t* r, uint32_t a) {
    asm volatile("ldmatrix.sync.aligned.m8n8.x4.shared.b16 {%0,%1,%2,%3},[%4];"
                 : "=r"(r[0]), "=r"(r[1]), "=r"(r[2]), "=r"(r[3]) : "r"(a));
}
__device__ __forceinline__ void ldm2(uint32_t* r, uint32_t a) {
    asm volatile("ldmatrix.sync.aligned.m8n8.x2.shared.b16 {%0,%1},[%2];"
                 : "=r"(r[0]), "=r"(r[1]) : "r"(a));
}
__device__ __forceinline__ void mma16816(float* d, const uint32_t* a, const uint32_t* b) {
    asm volatile("mma.sync.aligned.m16n8k16.row.col.f32.f16.f16.f32 "
                 "{%0,%1,%2,%3},{%4,%5,%6,%7},{%8,%9},{%0,%1,%2,%3};"
                 : "+f"(d[0]), "+f"(d[1]), "+f"(d[2]), "+f"(d[3])
                 : "r"(a[0]), "r"(a[1]), "r"(a[2]), "r"(a[3]), "r"(b[0]), "r"(b[1]));
}
#define CPA(dst, src) asm volatile("cp.async.cg.shared.global [%0], [%1], 16;" :: "r"(dst), "l"(src) : "memory")
#define CPC()         asm volatile("cp.async.commit_group;" ::: "memory")
#define CPW(n)        asm volatile("cp.async.wait_group %0;" :: "n"(n) : "memory")

// smem: 4 buffers x 4 regions (AH, AL, BH, BL); region = 128 rows x 48B
#define RAH 0
#define RAL 6144
#define RBH 12288
#define RBL 18432
#define BUFB 24576
#define NSTG 4
#define SMEM_TOT (NSTG * BUFB)   // 98304

__device__ __forceinline__ void split2(float v, __half& h, __half& l) {
    h = __float2half_rn(v);
    l = __float2half_rn(v - __half2float(h));
}

// ---------------------------------------------------------------------------
// MMA pipeline: C(128x128) = A(128xK) * B(128xK)^T, fp16 hi/lo 3-pass.
// ---------------------------------------------------------------------------
__device__ __forceinline__ void issue_stage(uint32_t sbuf,
        const __half* pAh, const __half* pAl, size_t sA,
        const __half* pBh, const __half* pBl, size_t sB,
        int k0, int tid) {
    const int row = tid >> 1, hc = tid & 1;
    const uint32_t doff = (uint32_t)row * 48 + hc * 16;
    const size_t ga = (size_t)row * sA + k0 + hc * 8;
    const size_t gb = (size_t)row * sB + k0 + hc * 8;
    CPA(sbuf + RAH + doff, pAh + ga);
    CPA(sbuf + RAL + doff, pAl + ga);
    CPA(sbuf + RBH + doff, pBh + gb);
    CPA(sbuf + RBL + doff, pBl + gb);
}

__device__ __forceinline__ void mma_pipe(
        const __half* pAh, const __half* pAl, size_t sA,
        const __half* pBh, const __half* pBl, size_t sB,
        int nst, float* __restrict__ out, size_t so) {
    extern __shared__ char smem[];
    const int tid  = threadIdx.x;
    const int lane = tid & 31;
    const int mo   = ((tid >> 5) & 3) * 32;   // 4 warps along M
    const int no   = (tid >> 7) * 64;         // 2 groups along N
    const uint32_t sbase = s2u(smem);

    const uint32_t a_off = (uint32_t)(lane & 15) * 48 + (uint32_t)(lane >> 4) * 16;
    const uint32_t b_off = (uint32_t)(lane & 7)  * 48 + (uint32_t)((lane >> 3) & 1) * 16;

    float acc[2][8][4];
    #pragma unroll
    for (int i = 0; i < 2; i++)
        #pragma unroll
        for (int j = 0; j < 8; j++)
            #pragma unroll
            for (int q = 0; q < 4; q++) acc[i][j][q] = 0.0f;

    // prologue: stages 0..2
    #pragma unroll
    for (int p = 0; p < NSTG - 1; p++) {
        issue_stage(sbase + p * BUFB, pAh, pAl, sA, pBh, pBl, sB, p * 16, tid);
        CPC();
    }

    for (int s = 0; s < nst; s++) {
        CPW(NSTG - 2);
        __syncthreads();
        if (s + NSTG - 1 < nst)
            issue_stage(sbase + ((s + NSTG - 1) & (NSTG - 1)) * BUFB,
                        pAh, pAl, sA, pBh, pBl, sB, (s + NSTG - 1) * 16, tid);
        CPC();

        const uint32_t bb = sbase + (uint32_t)(s & (NSTG - 1)) * BUFB;
        uint32_t ah[2][4], al[2][4];
        #pragma unroll
        for (int mi = 0; mi < 2; mi++) {
            uint32_t ro = (uint32_t)(mo + mi * 16) * 48;
            ldm4(ah[mi], bb + RAH + ro + a_off);
            ldm4(al[mi], bb + RAL + ro + a_off);
        }
        #pragma unroll
        for (int ni = 0; ni < 8; ni++) {
            uint32_t ro = (uint32_t)(no + ni * 8) * 48;
            uint32_t bh[2], bl[2];
            ldm2(bh, bb + RBH + ro + b_off);
            ldm2(bl, bb + RBL + ro + b_off);
            #pragma unroll
            for (int mi = 0; mi < 2; mi++) {
                mma16816(acc[mi][ni], ah[mi], bh);
                mma16816(acc[mi][ni], ah[mi], bl);
                mma16816(acc[mi][ni], al[mi], bh);
            }
        }
    }

    const int er = lane >> 2, ec = (lane & 3) * 2;
    #pragma unroll
    for (int mi = 0; mi < 2; mi++)
        #pragma unroll
        for (int ni = 0; ni < 8; ni++) {
            int r0 = mo + mi * 16 + er;
            int c  = no + ni * 8 + ec;
            *(float2*)(out + (size_t)r0 * so + c)       = make_float2(acc[mi][ni][0], acc[mi][ni][1]);
            *(float2*)(out + (size_t)(r0 + 8) * so + c) = make_float2(acc[mi][ni][2], acc[mi][ni][3]);
        }
}

// ---------------------------------------------------------------------------
// transpose + split: x[b][n][c] -> Xc_h/l [b][n][c], Xt_h/l [b][c][n]
// ---------------------------------------------------------------------------
__global__ void __launch_bounds__(256) split_kernel(const float* __restrict__ x) {
    __shared__ float sm[32][257];
    const int n0 = blockIdx.x * 32, c0 = blockIdx.y * 256, b = blockIdx.z;
    const int t = threadIdx.x;
    const float* Xb = x + (size_t)b * NDIM * CDIM;
    #pragma unroll
    for (int r = 0; r < 32; r++) sm[r][t] = Xb[(size_t)(n0 + r) * CDIM + c0 + t];
    __syncthreads();

    // row-major split
    const int cp = (t & 127) * 2;
    const int rh = t >> 7;
    #pragma unroll
    for (int rr = 0; rr < 16; rr++) {
        int r = rh * 16 + rr;
        __half h0, l0, h1, l1;
        split2(sm[r][cp], h0, l0);
        split2(sm[r][cp + 1], h1, l1);
        size_t o = ((size_t)b * NDIM + n0 + r) * CDIM + c0 + cp;
        *(__half2*)(g_Xc_h + o) = __halves2half2(h0, h1);
        *(__half2*)(g_Xc_l + o) = __halves2half2(l0, l1);
    }

    // transposed split
    #pragma unroll
    for (int g = 0; g < 8; g++) {
        __half hh[4], ll[4];
        #pragma unroll
        for (int j = 0; j < 4; j++) split2(sm[g * 4 + j][t], hh[j], ll[j]);
        size_t o = ((size_t)b * CDIM + c0 + t) * NDIM + n0 + g * 4;
        *(__half2*)(g_Xt_h + o)     = __halves2half2(hh[0], hh[1]);
        *(__half2*)(g_Xt_h + o + 2) = __halves2half2(hh[2], hh[3]);
        *(__half2*)(g_Xt_l + o)     = __halves2half2(ll[0], ll[1]);
        *(__half2*)(g_Xt_l + o + 2) = __halves2half2(ll[2], ll[3]);
    }
}

__global__ void __launch_bounds__(256, 2) gram_mma_kernel() {
    const int i0 = blockIdx.x * 128, j0 = blockIdx.y * 128, b = blockIdx.z;
    const size_t ob = (size_t)b * CDIM * NDIM;
    mma_pipe(g_Xt_h + ob + (size_t)i0 * NDIM, g_Xt_l + ob + (size_t)i0 * NDIM, NDIM,
             g_Xt_h + ob + (size_t)j0 * NDIM, g_Xt_l + ob + (size_t)j0 * NDIM, NDIM,
             NDIM / 16,
             g_energy + ((size_t)b * CDIM + i0) * CDIM + j0, CDIM);
}

__global__ void __launch_bounds__(256, 2) out_mma_kernel(float* __restrict__ y) {
    const int n0 = blockIdx.x * 128, i0 = blockIdx.y * 128, b = blockIdx.z;
    const size_t oa = (size_t)b * NDIM * CDIM + (size_t)n0 * CDIM;
    const size_t om = ((size_t)b * CDIM + i0) * CDIM;
    mma_pipe(g_Xc_h + oa, g_Xc_l + oa, CDIM,
             g_M_h + om, g_M_l + om, CDIM,
             CDIM / 16,
             y + ((size_t)b * NDIM + n0) * CDIM + i0, CDIM);
}

__global__ void __launch_bounds__(256) softmax_kernel(const float* __restrict__ gp) {
    const int i = blockIdx.x, b = blockIdx.y;
    const float* e = g_energy + ((size_t)b * CDIM + i) * CDIM;
    __shared__ float sm[256];
    const int t = threadIdx.x;
    float v0 = e[t], v1 = e[t + 256];
    sm[t] = fminf(v0, v1);
    __syncthreads();
    for (int s = 128; s > 0; s >>= 1) { if (t < s) sm[t] = fminf(sm[t], sm[t + s]); __syncthreads(); }
    float mn = sm[0];
    __syncthreads();
    float w0 = __expf(mn - v0), w1 = __expf(mn - v1);
    sm[t] = w0 + w1;
    __syncthreads();
    for (int s = 128; s > 0; s >>= 1) { if (t < s) sm[t] += sm[t + s]; __syncthreads(); }
    float inv = gp[0] / sm[0];
    size_t o = ((size_t)b * CDIM + i) * CDIM;
    float m0 = w0 * inv + (t == i ? 1.0f : 0.0f);
    float m1 = w1 * inv + (t + 256 == i ? 1.0f : 0.0f);
    __half h, l;
    split2(m0, h, l);  g_M_h[o + t] = h;        g_M_l[o + t] = l;
    split2(m1, h, l);  g_M_h[o + t + 256] = h;  g_M_l[o + t + 256] = l;
}

extern "C" void kernel_launch(void* const* d_in, const int* in_sizes, int n_in,
                              void* d_out, int out_size) {
    const float* x  = (const float*)d_in[0];
    const float* gm = (const float*)d_in[1];
    float*       y  = (float*)d_out;
    (void)in_sizes; (void)n_in; (void)out_size;

    cudaFuncSetAttribute(gram_mma_kernel, cudaFuncAttributeMaxDynamicSharedMemorySize, SMEM_TOT);
    cudaFuncSetAttribute(out_mma_kernel,  cudaFuncAttributeMaxDynamicSharedMemorySize, SMEM_TOT);

    split_kernel<<<dim3(NDIM / 32, CDIM / 256, BATCH), 256>>>(x);
    gram_mma_kernel<<<dim3(4, 4, BATCH), 256, SMEM_TOT>>>();
    softmax_kernel<<<dim3(CDIM, BATCH), 256>>>(gm);
    out_mma_kernel<<<dim3(NDIM / 128, 4, BATCH), 256, SMEM_TOT>>>(y);
}

// round 6
// speedup vs baseline: 1.3106x; 1.3106x over previous
#include <cuda_runtime.h>
#include <cuda_fp16.h>
#include <cstdint>

#define BATCH 8
#define NDIM  16384
#define CDIM  512
#define KSPLIT 4
#define KSEG  (NDIM / KSPLIT)   // 4096

__device__ __half g_Xt_h[(size_t)BATCH * CDIM * NDIM];  // [b][c][n]
__device__ __half g_Xt_l[(size_t)BATCH * CDIM * NDIM];
__device__ __half g_Xc_h[(size_t)BATCH * NDIM * CDIM];  // [b][n][c]
__device__ __half g_Xc_l[(size_t)BATCH * NDIM * CDIM];
__device__ __half g_M_h[(size_t)BATCH * CDIM * CDIM];   // [b][i][k]
__device__ __half g_M_l[(size_t)BATCH * CDIM * CDIM];
__device__ float  g_Epart[(size_t)KSPLIT * BATCH * CDIM * CDIM];

// ---- helpers -------------------------------------------------------------
__device__ __forceinline__ uint32_t s2u(const void* p) {
    uint32_t a;
    asm("{ .reg .u64 t; cvta.to.shared.u64 t, %1; cvt.u32.u64 %0, t; }" : "=r"(a) : "l"(p));
    return a;
}
__device__ __forceinline__ void ldm4(uint32_t* r, uint32_t a) {
    asm volatile("ldmatrix.sync.aligned.m8n8.x4.shared.b16 {%0,%1,%2,%3},[%4];"
                 : "=r"(r[0]), "=r"(r[1]), "=r"(r[2]), "=r"(r[3]) : "r"(a));
}
__device__ __forceinline__ void mma16816(float* d, const uint32_t* a, const uint32_t* b) {
    asm volatile("mma.sync.aligned.m16n8k16.row.col.f32.f16.f16.f32 "
                 "{%0,%1,%2,%3},{%4,%5,%6,%7},{%8,%9},{%0,%1,%2,%3};"
                 : "+f"(d[0]), "+f"(d[1]), "+f"(d[2]), "+f"(d[3])
                 : "r"(a[0]), "r"(a[1]), "r"(a[2]), "r"(a[3]), "r"(b[0]), "r"(b[1]));
}
#define CPA(dst, src) asm volatile("cp.async.cg.shared.global [%0], [%1], 16;" :: "r"(dst), "l"(src) : "memory")
#define CPC()         asm volatile("cp.async.commit_group;" ::: "memory")
#define CPW(n)        asm volatile("cp.async.wait_group %0;" :: "n"(n) : "memory")

// smem: 4 buffers x 4 regions (AH, AL, BH, BL); region = 128 rows x 48B
#define RAH 0
#define RAL 6144
#define RBH 12288
#define RBL 18432
#define BUFB 24576
#define NSTG 4
#define SMEM_TOT (NSTG * BUFB)   // 98304
#define SPLIT_SMEM (64 * 257 * 4)

__device__ __forceinline__ void sp2(float a, float b, uint32_t& hp, uint32_t& lp) {
    __half ha = __float2half_rn(a), hb = __float2half_rn(b);
    __half la = __float2half_rn(a - __half2float(ha));
    __half lb = __float2half_rn(b - __half2float(hb));
    __half2 H = __halves2half2(ha, hb), L = __halves2half2(la, lb);
    hp = *reinterpret_cast<uint32_t*>(&H);
    lp = *reinterpret_cast<uint32_t*>(&L);
}

// ---------------------------------------------------------------------------
// cp.async stage fill (unchanged from R5): 128 rows x 16 halves per region
// ---------------------------------------------------------------------------
__device__ __forceinline__ void issue_stage(uint32_t sbuf,
        const __half* pAh, const __half* pAl, size_t sA,
        const __half* pBh, const __half* pBl, size_t sB,
        int k0, int tid) {
    const int row = tid >> 1, hc = tid & 1;
    const uint32_t doff = (uint32_t)row * 48 + hc * 16;
    const size_t ga = (size_t)row * sA + k0 + hc * 8;
    const size_t gb = (size_t)row * sB + k0 + hc * 8;
    CPA(sbuf + RAH + doff, pAh + ga);
    CPA(sbuf + RAL + doff, pAl + ga);
    CPA(sbuf + RBH + doff, pBh + gb);
    CPA(sbuf + RBL + doff, pBl + gb);
}

// ---------------------------------------------------------------------------
// core: acc(128x128) = A(128xK) * B(128xK)^T, fp16 hi/lo 3-pass, paired ldm4 B
// ---------------------------------------------------------------------------
__device__ __forceinline__ void mma_core(
        const __half* pAh, const __half* pAl, size_t sA,
        const __half* pBh, const __half* pBl, size_t sB,
        int nst, float (&acc)[2][8][4]) {
    extern __shared__ char smem[];
    const int tid  = threadIdx.x;
    const int lane = tid & 31;
    const int mo   = ((tid >> 5) & 3) * 32;
    const int no   = (tid >> 7) * 64;
    const uint32_t sbase = s2u(smem);

    const uint32_t a_off = (uint32_t)(lane & 15) * 48 + (uint32_t)(lane >> 4) * 16;
    // paired-B ldm4: m0,m1 -> (b0,b1) of ni ; m2,m3 -> (b0,b1) of ni+1
    const uint32_t bpo = (uint32_t)((lane & 7) + ((lane >> 4) & 1) * 8) * 48
                       + (uint32_t)((lane >> 3) & 1) * 16;

    #pragma unroll
    for (int i = 0; i < 2; i++)
        #pragma unroll
        for (int j = 0; j < 8; j++)
            #pragma unroll
            for (int q = 0; q < 4; q++) acc[i][j][q] = 0.0f;

    #pragma unroll
    for (int p = 0; p < NSTG - 1; p++) {
        issue_stage(sbase + p * BUFB, pAh, pAl, sA, pBh, pBl, sB, p * 16, tid);
        CPC();
    }

    for (int s = 0; s < nst; s++) {
        CPW(NSTG - 2);
        __syncthreads();
        if (s + NSTG - 1 < nst)
            issue_stage(sbase + ((s + NSTG - 1) & (NSTG - 1)) * BUFB,
                        pAh, pAl, sA, pBh, pBl, sB, (s + NSTG - 1) * 16, tid);
        CPC();

        const uint32_t bb = sbase + (uint32_t)(s & (NSTG - 1)) * BUFB;
        uint32_t ah[2][4], al[2][4];
        #pragma unroll
        for (int mi = 0; mi < 2; mi++) {
            uint32_t ro = (uint32_t)(mo + mi * 16) * 48;
            ldm4(ah[mi], bb + RAH + ro + a_off);
            ldm4(al[mi], bb + RAL + ro + a_off);
        }
        uint32_t bhp[2][4], blp[2][4];
        ldm4(bhp[0], bb + RBH + (uint32_t)no * 48 + bpo);
        ldm4(blp[0], bb + RBL + (uint32_t)no * 48 + bpo);
        #pragma unroll
        for (int p = 0; p < 4; p++) {
            if (p < 3) {
                uint32_t ro = (uint32_t)(no + (p + 1) * 16) * 48;
                ldm4(bhp[(p + 1) & 1], bb + RBH + ro + bpo);
                ldm4(blp[(p + 1) & 1], bb + RBL + ro + bpo);
            }
            uint32_t* ch = bhp[p & 1];
            uint32_t* cl = blp[p & 1];
            #pragma unroll
            for (int hf = 0; hf < 2; hf++) {
                int ni = p * 2 + hf;
                #pragma unroll
                for (int mi = 0; mi < 2; mi++) {
                    mma16816(acc[mi][ni], ah[mi], ch + hf * 2);
                    mma16816(acc[mi][ni], ah[mi], cl + hf * 2);
                    mma16816(acc[mi][ni], al[mi], ch + hf * 2);
                }
            }
        }
    }
    CPW(0);
    __syncthreads();
}

__device__ __forceinline__ void epilogue_direct(const float (&acc)[2][8][4],
                                                float* out, size_t so) {
    const int tid  = threadIdx.x;
    const int lane = tid & 31;
    const int mo   = ((tid >> 5) & 3) * 32;
    const int no   = (tid >> 7) * 64;
    const int er = lane >> 2, ec = (lane & 3) * 2;
    #pragma unroll
    for (int mi = 0; mi < 2; mi++)
        #pragma unroll
        for (int ni = 0; ni < 8; ni++) {
            int r0 = mo + mi * 16 + er;
            int c  = no + ni * 8 + ec;
            *(float2*)(out + (size_t)r0 * so + c)       = make_float2(acc[mi][ni][0], acc[mi][ni][1]);
            *(float2*)(out + (size_t)(r0 + 8) * so + c) = make_float2(acc[mi][ni][2], acc[mi][ni][3]);
        }
}

// ---------------------------------------------------------------------------
// split: x[b][n][c] -> Xc_h/l (row-major) + Xt_h/l (transposed), all 128B stores
// ---------------------------------------------------------------------------
__global__ void __launch_bounds__(256) split_kernel(const float* __restrict__ x) {
    extern __shared__ float sm[];  // [64][257]
    const int n0 = blockIdx.x * 64, c0 = blockIdx.y * 256, b = blockIdx.z;
    const int t = threadIdx.x;
    const float* Xb = x + (size_t)b * NDIM * CDIM;
    #pragma unroll
    for (int r = 0; r < 64; r++) sm[r * 257 + t] = Xb[(size_t)(n0 + r) * CDIM + c0 + t];
    __syncthreads();

    // row-major: thread -> n-row (t>>2), 64-c chunk ((t&3)*64). 128B stores.
    {
        const int r = t >> 2, cc = (t & 3) * 64;
        uint32_t hp[32], lp[32];
        #pragma unroll
        for (int q = 0; q < 32; q++)
            sp2(sm[r * 257 + cc + 2 * q], sm[r * 257 + cc + 2 * q + 1], hp[q], lp[q]);
        size_t o = ((size_t)b * NDIM + n0 + r) * CDIM + c0 + cc;
        #pragma unroll
        for (int q = 0; q < 8; q++) {
            *(uint4*)(g_Xc_h + o + q * 8) = make_uint4(hp[4*q], hp[4*q+1], hp[4*q+2], hp[4*q+3]);
            *(uint4*)(g_Xc_l + o + q * 8) = make_uint4(lp[4*q], lp[4*q+1], lp[4*q+2], lp[4*q+3]);
        }
    }
    // transposed: thread -> channel c0+t, 64 n. 128B stores.
    {
        uint32_t hp[32], lp[32];
        #pragma unroll
        for (int q = 0; q < 32; q++)
            sp2(sm[(2 * q) * 257 + t], sm[(2 * q + 1) * 257 + t], hp[q], lp[q]);
        size_t o = ((size_t)b * CDIM + c0 + t) * NDIM + n0;
        #pragma unroll
        for (int q = 0; q < 8; q++) {
            *(uint4*)(g_Xt_h + o + q * 8) = make_uint4(hp[4*q], hp[4*q+1], hp[4*q+2], hp[4*q+3]);
            *(uint4*)(g_Xt_l + o + q * 8) = make_uint4(lp[4*q], lp[4*q+1], lp[4*q+2], lp[4*q+3]);
        }
    }
}

// ---------------------------------------------------------------------------
// gram: upper-triangle tiles + 4-way K split; partial E to g_Epart
// ---------------------------------------------------------------------------
__global__ void __launch_bounds__(256, 2) gram_mma_kernel() {
    const int IT[10] = {0,0,0,0,1,1,1,2,2,3};
    const int JT[10] = {0,1,2,3,1,2,3,2,3,3};
    const int pi = blockIdx.x, ks = blockIdx.y, b = blockIdx.z;
    const int it = IT[pi], jt = JT[pi];
    const int i0 = it * 128, j0 = jt * 128;
    const size_t ob = (size_t)b * CDIM * NDIM;
    const size_t ka = (size_t)ks * KSEG;

    float acc[2][8][4];
    mma_core(g_Xt_h + ob + (size_t)i0 * NDIM + ka, g_Xt_l + ob + (size_t)i0 * NDIM + ka, NDIM,
             g_Xt_h + ob + (size_t)j0 * NDIM + ka, g_Xt_l + ob + (size_t)j0 * NDIM + ka, NDIM,
             KSEG / 16, acc);

    float* Ep = g_Epart + (((size_t)ks * BATCH + b) * CDIM + i0) * CDIM + j0;
    epilogue_direct(acc, Ep, CDIM);

    if (it != jt) {
        // transpose via smem, write mirror tile coalesced
        extern __shared__ char smemc[];
        float* ts = (float*)smemc;  // stride 132
        const int tid = threadIdx.x, lane = tid & 31;
        const int mo = ((tid >> 5) & 3) * 32, no = (tid >> 7) * 64;
        const int er = lane >> 2, ec = (lane & 3) * 2;
        __syncthreads();
        #pragma unroll
        for (int mi = 0; mi < 2; mi++)
            #pragma unroll
            for (int ni = 0; ni < 8; ni++) {
                int r0 = mo + mi * 16 + er, c = no + ni * 8 + ec;
                ts[r0 * 132 + c]         = acc[mi][ni][0];
                ts[r0 * 132 + c + 1]     = acc[mi][ni][1];
                ts[(r0 + 8) * 132 + c]     = acc[mi][ni][2];
                ts[(r0 + 8) * 132 + c + 1] = acc[mi][ni][3];
            }
        __syncthreads();
        float* Em = g_Epart + (((size_t)ks * BATCH + b) * CDIM + j0) * CDIM + i0;
        const int j = tid >> 1, hf = tid & 1;
        float* dst = Em + (size_t)j * CDIM + hf * 64;
        #pragma unroll
        for (int w = 0; w < 16; w++) {
            float4 v = make_float4(ts[(hf * 64 + 4 * w) * 132 + j],
                                   ts[(hf * 64 + 4 * w + 1) * 132 + j],
                                   ts[(hf * 64 + 4 * w + 2) * 132 + j],
                                   ts[(hf * 64 + 4 * w + 3) * 132 + j]);
            *(float4*)(dst + 4 * w) = v;
        }
    }
}

// ---------------------------------------------------------------------------
__global__ void __launch_bounds__(256, 2) out_mma_kernel(float* __restrict__ y) {
    const int n0 = blockIdx.x * 128, i0 = blockIdx.y * 128, b = blockIdx.z;
    const size_t oa = (size_t)b * NDIM * CDIM + (size_t)n0 * CDIM;
    const size_t om = ((size_t)b * CDIM + i0) * CDIM;
    float acc[2][8][4];
    mma_core(g_Xc_h + oa, g_Xc_l + oa, CDIM,
             g_M_h + om, g_M_l + om, CDIM,
             CDIM / 16, acc);
    epilogue_direct(acc, y + ((size_t)b * NDIM + n0) * CDIM + i0, CDIM);
}

// softmax(-E) row i over summed K-partials; M[i][k] = gamma*att + (i==k)
__global__ void __launch_bounds__(256) softmax_kernel(const float* __restrict__ gp) {
    const int i = blockIdx.x, b = blockIdx.y;
    __shared__ float sm[256];
    const int t = threadIdx.x;
    float v0 = 0.0f, v1 = 0.0f;
    #pragma unroll
    for (int ks = 0; ks < KSPLIT; ks++) {
        const float* e = g_Epart + (((size_t)ks * BATCH + b) * CDIM + i) * CDIM;
        v0 += e[t];
        v1 += e[t + 256];
    }
    sm[t] = fminf(v0, v1);
    __syncthreads();
    for (int s = 128; s > 0; s >>= 1) { if (t < s) sm[t] = fminf(sm[t], sm[t + s]); __syncthreads(); }
    float mn = sm[0];
    __syncthreads();
    float w0 = __expf(mn - v0), w1 = __expf(mn - v1);
    sm[t] = w0 + w1;
    __syncthreads();
    for (int s = 128; s > 0; s >>= 1) { if (t < s) sm[t] += sm[t + s]; __syncthreads(); }
    float inv = gp[0] / sm[0];
    size_t o = ((size_t)b * CDIM + i) * CDIM;
    float m0 = w0 * inv + (t == i ? 1.0f : 0.0f);
    float m1 = w1 * inv + (t + 256 == i ? 1.0f : 0.0f);
    uint32_t hp, lp;
    sp2(m0, 0.0f, hp, lp);
    g_M_h[o + t] = *(__half*)&hp;  g_M_l[o + t] = *(__half*)&lp;
    sp2(m1, 0.0f, hp, lp);
    g_M_h[o + t + 256] = *(__half*)&hp;  g_M_l[o + t + 256] = *(__half*)&lp;
}

extern "C" void kernel_launch(void* const* d_in, const int* in_sizes, int n_in,
                              void* d_out, int out_size) {
    const float* x  = (const float*)d_in[0];
    const float* gm = (const float*)d_in[1];
    float*       y  = (float*)d_out;
    (void)in_sizes; (void)n_in; (void)out_size;

    cudaFuncSetAttribute(split_kernel,    cudaFuncAttributeMaxDynamicSharedMemorySize, SPLIT_SMEM);
    cudaFuncSetAttribute(gram_mma_kernel, cudaFuncAttributeMaxDynamicSharedMemorySize, SMEM_TOT);
    cudaFuncSetAttribute(out_mma_kernel,  cudaFuncAttributeMaxDynamicSharedMemorySize, SMEM_TOT);

    split_kernel<<<dim3(NDIM / 64, CDIM / 256, BATCH), 256, SPLIT_SMEM>>>(x);
    gram_mma_kernel<<<dim3(10, KSPLIT, BATCH), 256, SMEM_TOT>>>();
    softmax_kernel<<<dim3(CDIM, BATCH), 256>>>(gm);
    out_mma_kernel<<<dim3(NDIM / 128, 4, BATCH), 256, SMEM_TOT>>>(y);
}

// round 7
// speedup vs baseline: 1.7890x; 1.3650x over previous
#include <cuda_runtime.h>
#include <cuda_fp16.h>
#include <cstdint>

#define BATCH 8
#define NDIM  16384
#define CDIM  512
#define KSPLIT 4
#define KSEG  (NDIM / KSPLIT)   // 4096

__device__ __half g_Xt_h[(size_t)BATCH * CDIM * NDIM];  // [b][c][n]
__device__ __half g_Xt_l[(size_t)BATCH * CDIM * NDIM];
__device__ __half g_Xc_h[(size_t)BATCH * NDIM * CDIM];  // [b][n][c]
__device__ __half g_M_h[(size_t)BATCH * CDIM * CDIM];   // [b][i][k] = gamma*att (no identity)
__device__ float  g_Epart[(size_t)KSPLIT * BATCH * CDIM * CDIM];

// ---- helpers -------------------------------------------------------------
__device__ __forceinline__ uint32_t s2u(const void* p) {
    uint32_t a;
    asm("{ .reg .u64 t; cvta.to.shared.u64 t, %1; cvt.u32.u64 %0, t; }" : "=r"(a) : "l"(p));
    return a;
}
__device__ __forceinline__ void ldm4(uint32_t* r, uint32_t a) {
    asm volatile("ldmatrix.sync.aligned.m8n8.x4.shared.b16 {%0,%1,%2,%3},[%4];"
                 : "=r"(r[0]), "=r"(r[1]), "=r"(r[2]), "=r"(r[3]) : "r"(a));
}
__device__ __forceinline__ void mma16816(float* d, const uint32_t* a, const uint32_t* b) {
    asm volatile("mma.sync.aligned.m16n8k16.row.col.f32.f16.f16.f32 "
                 "{%0,%1,%2,%3},{%4,%5,%6,%7},{%8,%9},{%0,%1,%2,%3};"
                 : "+f"(d[0]), "+f"(d[1]), "+f"(d[2]), "+f"(d[3])
                 : "r"(a[0]), "r"(a[1]), "r"(a[2]), "r"(a[3]), "r"(b[0]), "r"(b[1]));
}
#define CPA(dst, src) asm volatile("cp.async.cg.shared.global [%0], [%1], 16;" :: "r"(dst), "l"(src) : "memory")
#define CPC()         asm volatile("cp.async.commit_group;" ::: "memory")
#define CPW(n)        asm volatile("cp.async.wait_group %0;" :: "n"(n) : "memory")

// 3-pass (gram) smem: 4 buffers x 4 regions; region = 128 rows x 48B
#define RAH 0
#define RAL 6144
#define RBH 12288
#define RBL 18432
#define BUFB 24576
#define NSTG 4
#define SMEM_TOT (NSTG * BUFB)      // 98304
// 1-pass (out) smem: 4 buffers x 2 regions
#define O_RA 0
#define O_RB 6144
#define O_BUFB 12288
#define O_SMEM (NSTG * O_BUFB)      // 49152
#define SPLIT_SMEM (64 * 257 * 4)

__device__ __forceinline__ void sp2(float a, float b, uint32_t& hp, uint32_t& lp) {
    __half ha = __float2half_rn(a), hb = __float2half_rn(b);
    __half la = __float2half_rn(a - __half2float(ha));
    __half lb = __float2half_rn(b - __half2float(hb));
    __half2 H = __halves2half2(ha, hb), L = __halves2half2(la, lb);
    hp = *reinterpret_cast<uint32_t*>(&H);
    lp = *reinterpret_cast<uint32_t*>(&L);
}

// ---------------------------------------------------------------------------
// 3-pass core (gram)
// ---------------------------------------------------------------------------
__device__ __forceinline__ void issue_stage3(uint32_t sbuf,
        const __half* pAh, const __half* pAl, size_t sA,
        const __half* pBh, const __half* pBl, size_t sB,
        int k0, int tid) {
    const int row = tid >> 1, hc = tid & 1;
    const uint32_t doff = (uint32_t)row * 48 + hc * 16;
    const size_t ga = (size_t)row * sA + k0 + hc * 8;
    const size_t gb = (size_t)row * sB + k0 + hc * 8;
    CPA(sbuf + RAH + doff, pAh + ga);
    CPA(sbuf + RAL + doff, pAl + ga);
    CPA(sbuf + RBH + doff, pBh + gb);
    CPA(sbuf + RBL + doff, pBl + gb);
}

__device__ __forceinline__ void mma_core3(
        const __half* pAh, const __half* pAl, size_t sA,
        const __half* pBh, const __half* pBl, size_t sB,
        int nst, float (&acc)[2][8][4]) {
    extern __shared__ char smem[];
    const int tid  = threadIdx.x;
    const int lane = tid & 31;
    const int mo   = ((tid >> 5) & 3) * 32;
    const int no   = (tid >> 7) * 64;
    const uint32_t sbase = s2u(smem);

    const uint32_t a_off = (uint32_t)(lane & 15) * 48 + (uint32_t)(lane >> 4) * 16;
    const uint32_t bpo = (uint32_t)((lane & 7) + ((lane >> 4) & 1) * 8) * 48
                       + (uint32_t)((lane >> 3) & 1) * 16;

    #pragma unroll
    for (int i = 0; i < 2; i++)
        #pragma unroll
        for (int j = 0; j < 8; j++)
            #pragma unroll
            for (int q = 0; q < 4; q++) acc[i][j][q] = 0.0f;

    #pragma unroll
    for (int p = 0; p < NSTG - 1; p++) {
        issue_stage3(sbase + p * BUFB, pAh, pAl, sA, pBh, pBl, sB, p * 16, tid);
        CPC();
    }

    for (int s = 0; s < nst; s++) {
        CPW(NSTG - 2);
        __syncthreads();
        if (s + NSTG - 1 < nst)
            issue_stage3(sbase + ((s + NSTG - 1) & (NSTG - 1)) * BUFB,
                         pAh, pAl, sA, pBh, pBl, sB, (s + NSTG - 1) * 16, tid);
        CPC();

        const uint32_t bb = sbase + (uint32_t)(s & (NSTG - 1)) * BUFB;
        uint32_t ah[2][4], al[2][4];
        #pragma unroll
        for (int mi = 0; mi < 2; mi++) {
            uint32_t ro = (uint32_t)(mo + mi * 16) * 48;
            ldm4(ah[mi], bb + RAH + ro + a_off);
            ldm4(al[mi], bb + RAL + ro + a_off);
        }
        uint32_t bhp[2][4], blp[2][4];
        ldm4(bhp[0], bb + RBH + (uint32_t)no * 48 + bpo);
        ldm4(blp[0], bb + RBL + (uint32_t)no * 48 + bpo);
        #pragma unroll
        for (int p = 0; p < 4; p++) {
            if (p < 3) {
                uint32_t ro = (uint32_t)(no + (p + 1) * 16) * 48;
                ldm4(bhp[(p + 1) & 1], bb + RBH + ro + bpo);
                ldm4(blp[(p + 1) & 1], bb + RBL + ro + bpo);
            }
            uint32_t* ch = bhp[p & 1];
            uint32_t* cl = blp[p & 1];
            #pragma unroll
            for (int hf = 0; hf < 2; hf++) {
                int ni = p * 2 + hf;
                #pragma unroll
                for (int mi = 0; mi < 2; mi++) {
                    mma16816(acc[mi][ni], ah[mi], ch + hf * 2);
                    mma16816(acc[mi][ni], ah[mi], cl + hf * 2);
                    mma16816(acc[mi][ni], al[mi], ch + hf * 2);
                }
            }
        }
    }
    CPW(0);
    __syncthreads();
}

__device__ __forceinline__ void epilogue_direct(const float (&acc)[2][8][4],
                                                float* out, size_t so) {
    const int tid  = threadIdx.x;
    const int lane = tid & 31;
    const int mo   = ((tid >> 5) & 3) * 32;
    const int no   = (tid >> 7) * 64;
    const int er = lane >> 2, ec = (lane & 3) * 2;
    #pragma unroll
    for (int mi = 0; mi < 2; mi++)
        #pragma unroll
        for (int ni = 0; ni < 8; ni++) {
            int r0 = mo + mi * 16 + er;
            int c  = no + ni * 8 + ec;
            *(float2*)(out + (size_t)r0 * so + c)       = make_float2(acc[mi][ni][0], acc[mi][ni][1]);
            *(float2*)(out + (size_t)(r0 + 8) * so + c) = make_float2(acc[mi][ni][2], acc[mi][ni][3]);
        }
}

// ---------------------------------------------------------------------------
// split: x[b][n][c] -> Xc_h (row-major) + Xt_h/l (transposed)
// ---------------------------------------------------------------------------
__global__ void __launch_bounds__(256) split_kernel(const float* __restrict__ x) {
    extern __shared__ float sm[];  // [64][257]
    const int n0 = blockIdx.x * 64, c0 = blockIdx.y * 256, b = blockIdx.z;
    const int t = threadIdx.x;
    const float* Xb = x + (size_t)b * NDIM * CDIM;
    #pragma unroll
    for (int r = 0; r < 64; r++) sm[r * 257 + t] = Xb[(size_t)(n0 + r) * CDIM + c0 + t];
    __syncthreads();

    {   // row-major hi only
        const int r = t >> 2, cc = (t & 3) * 64;
        uint32_t hp[32], lp;
        #pragma unroll
        for (int q = 0; q < 32; q++)
            sp2(sm[r * 257 + cc + 2 * q], sm[r * 257 + cc + 2 * q + 1], hp[q], lp);
        size_t o = ((size_t)b * NDIM + n0 + r) * CDIM + c0 + cc;
        #pragma unroll
        for (int q = 0; q < 8; q++)
            *(uint4*)(g_Xc_h + o + q * 8) = make_uint4(hp[4*q], hp[4*q+1], hp[4*q+2], hp[4*q+3]);
    }
    {   // transposed hi+lo
        uint32_t hp[32], lp[32];
        #pragma unroll
        for (int q = 0; q < 32; q++)
            sp2(sm[(2 * q) * 257 + t], sm[(2 * q + 1) * 257 + t], hp[q], lp[q]);
        size_t o = ((size_t)b * CDIM + c0 + t) * NDIM + n0;
        #pragma unroll
        for (int q = 0; q < 8; q++) {
            *(uint4*)(g_Xt_h + o + q * 8) = make_uint4(hp[4*q], hp[4*q+1], hp[4*q+2], hp[4*q+3]);
            *(uint4*)(g_Xt_l + o + q * 8) = make_uint4(lp[4*q], lp[4*q+1], lp[4*q+2], lp[4*q+3]);
        }
    }
}

// ---------------------------------------------------------------------------
// gram: upper-triangle tiles + 4-way K split (3-pass)
// ---------------------------------------------------------------------------
__global__ void __launch_bounds__(256, 2) gram_mma_kernel() {
    const int IT[10] = {0,0,0,0,1,1,1,2,2,3};
    const int JT[10] = {0,1,2,3,1,2,3,2,3,3};
    const int pi = blockIdx.x, ks = blockIdx.y, b = blockIdx.z;
    const int it = IT[pi], jt = JT[pi];
    const int i0 = it * 128, j0 = jt * 128;
    const size_t ob = (size_t)b * CDIM * NDIM;
    const size_t ka = (size_t)ks * KSEG;

    float acc[2][8][4];
    mma_core3(g_Xt_h + ob + (size_t)i0 * NDIM + ka, g_Xt_l + ob + (size_t)i0 * NDIM + ka, NDIM,
              g_Xt_h + ob + (size_t)j0 * NDIM + ka, g_Xt_l + ob + (size_t)j0 * NDIM + ka, NDIM,
              KSEG / 16, acc);

    float* Ep = g_Epart + (((size_t)ks * BATCH + b) * CDIM + i0) * CDIM + j0;
    epilogue_direct(acc, Ep, CDIM);

    if (it != jt) {
        extern __shared__ char smemc[];
        float* ts = (float*)smemc;  // stride 132
        const int tid = threadIdx.x, lane = tid & 31;
        const int mo = ((tid >> 5) & 3) * 32, no = (tid >> 7) * 64;
        const int er = lane >> 2, ec = (lane & 3) * 2;
        __syncthreads();
        #pragma unroll
        for (int mi = 0; mi < 2; mi++)
            #pragma unroll
            for (int ni = 0; ni < 8; ni++) {
                int r0 = mo + mi * 16 + er, c = no + ni * 8 + ec;
                ts[r0 * 132 + c]           = acc[mi][ni][0];
                ts[r0 * 132 + c + 1]       = acc[mi][ni][1];
                ts[(r0 + 8) * 132 + c]     = acc[mi][ni][2];
                ts[(r0 + 8) * 132 + c + 1] = acc[mi][ni][3];
            }
        __syncthreads();
        float* Em = g_Epart + (((size_t)ks * BATCH + b) * CDIM + j0) * CDIM + i0;
        const int j = tid >> 1, hf = tid & 1;
        float* dst = Em + (size_t)j * CDIM + hf * 64;
        #pragma unroll
        for (int w = 0; w < 16; w++) {
            float4 v = make_float4(ts[(hf * 64 + 4 * w) * 132 + j],
                                   ts[(hf * 64 + 4 * w + 1) * 132 + j],
                                   ts[(hf * 64 + 4 * w + 2) * 132 + j],
                                   ts[(hf * 64 + 4 * w + 3) * 132 + j]);
            *(float4*)(dst + 4 * w) = v;
        }
    }
}

// ---------------------------------------------------------------------------
// out: Y = Xc_h * M'^T (single fp16 pass) + x  (exact fp32 residual)
// ---------------------------------------------------------------------------
__global__ void __launch_bounds__(256, 2) out_mma_kernel(const float* __restrict__ x,
                                                         float* __restrict__ y) {
    extern __shared__ char smem[];
    const int n0 = blockIdx.x * 128, i0 = blockIdx.y * 128, b = blockIdx.z;
    const __half* pA = g_Xc_h + (size_t)b * NDIM * CDIM + (size_t)n0 * CDIM;
    const __half* pB = g_M_h + ((size_t)b * CDIM + i0) * CDIM;

    const int tid  = threadIdx.x;
    const int lane = tid & 31;
    const int mo   = ((tid >> 5) & 3) * 32;
    const int no   = (tid >> 7) * 64;
    const uint32_t sbase = s2u(smem);

    const uint32_t a_off = (uint32_t)(lane & 15) * 48 + (uint32_t)(lane >> 4) * 16;
    const uint32_t bpo = (uint32_t)((lane & 7) + ((lane >> 4) & 1) * 8) * 48
                       + (uint32_t)((lane >> 3) & 1) * 16;

    float acc[2][8][4];
    #pragma unroll
    for (int i = 0; i < 2; i++)
        #pragma unroll
        for (int j = 0; j < 8; j++)
            #pragma unroll
            for (int q = 0; q < 4; q++) acc[i][j][q] = 0.0f;

    const int row = tid >> 1, hc = tid & 1;
    const uint32_t doff = (uint32_t)row * 48 + hc * 16;

    #pragma unroll
    for (int p = 0; p < NSTG - 1; p++) {
        uint32_t sbuf = sbase + p * O_BUFB;
        CPA(sbuf + O_RA + doff, pA + (size_t)row * CDIM + p * 16 + hc * 8);
        CPA(sbuf + O_RB + doff, pB + (size_t)row * CDIM + p * 16 + hc * 8);
        CPC();
    }

    const int nst = CDIM / 16;
    for (int s = 0; s < nst; s++) {
        CPW(NSTG - 2);
        __syncthreads();
        if (s + NSTG - 1 < nst) {
            uint32_t sbuf = sbase + ((s + NSTG - 1) & (NSTG - 1)) * O_BUFB;
            int k0 = (s + NSTG - 1) * 16;
            CPA(sbuf + O_RA + doff, pA + (size_t)row * CDIM + k0 + hc * 8);
            CPA(sbuf + O_RB + doff, pB + (size_t)row * CDIM + k0 + hc * 8);
        }
        CPC();

        const uint32_t bb = sbase + (uint32_t)(s & (NSTG - 1)) * O_BUFB;
        uint32_t ah[2][4];
        #pragma unroll
        for (int mi = 0; mi < 2; mi++)
            ldm4(ah[mi], bb + O_RA + (uint32_t)(mo + mi * 16) * 48 + a_off);
        uint32_t bhp[2][4];
        ldm4(bhp[0], bb + O_RB + (uint32_t)no * 48 + bpo);
        #pragma unroll
        for (int p = 0; p < 4; p++) {
            if (p < 3)
                ldm4(bhp[(p + 1) & 1], bb + O_RB + (uint32_t)(no + (p + 1) * 16) * 48 + bpo);
            uint32_t* ch = bhp[p & 1];
            #pragma unroll
            for (int hf = 0; hf < 2; hf++) {
                int ni = p * 2 + hf;
                #pragma unroll
                for (int mi = 0; mi < 2; mi++)
                    mma16816(acc[mi][ni], ah[mi], ch + hf * 2);
            }
        }
    }
    CPW(0);
    __syncthreads();

    // epilogue: add exact fp32 residual x[n][i]
    const float* xr = x + ((size_t)b * NDIM + n0) * CDIM + i0;
    float* yr = y + ((size_t)b * NDIM + n0) * CDIM + i0;
    const int er = lane >> 2, ec = (lane & 3) * 2;
    #pragma unroll
    for (int mi = 0; mi < 2; mi++)
        #pragma unroll
        for (int ni = 0; ni < 8; ni++) {
            int r0 = mo + mi * 16 + er;
            int c  = no + ni * 8 + ec;
            float2 x0 = *(const float2*)(xr + (size_t)r0 * CDIM + c);
            float2 x1 = *(const float2*)(xr + (size_t)(r0 + 8) * CDIM + c);
            *(float2*)(yr + (size_t)r0 * CDIM + c) =
                make_float2(acc[mi][ni][0] + x0.x, acc[mi][ni][1] + x0.y);
            *(float2*)(yr + (size_t)(r0 + 8) * CDIM + c) =
                make_float2(acc[mi][ni][2] + x1.x, acc[mi][ni][3] + x1.y);
        }
}

// softmax(-E) over summed K-partials; M'[i][k] = gamma*att[i][k]  (fp16)
__global__ void __launch_bounds__(256) softmax_kernel(const float* __restrict__ gp) {
    const int i = blockIdx.x, b = blockIdx.y;
    __shared__ float sm[256];
    const int t = threadIdx.x;
    float v0 = 0.0f, v1 = 0.0f;
    #pragma unroll
    for (int ks = 0; ks < KSPLIT; ks++) {
        const float* e = g_Epart + (((size_t)ks * BATCH + b) * CDIM + i) * CDIM;
        v0 += e[t];
        v1 += e[t + 256];
    }
    sm[t] = fminf(v0, v1);
    __syncthreads();
    for (int s = 128; s > 0; s >>= 1) { if (t < s) sm[t] = fminf(sm[t], sm[t + s]); __syncthreads(); }
    float mn = sm[0];
    __syncthreads();
    float w0 = __expf(mn - v0), w1 = __expf(mn - v1);
    sm[t] = w0 + w1;
    __syncthreads();
    for (int s = 128; s > 0; s >>= 1) { if (t < s) sm[t] += sm[t + s]; __syncthreads(); }
    float inv = gp[0] / sm[0];
    size_t o = ((size_t)b * CDIM + i) * CDIM;
    g_M_h[o + t]       = __float2half_rn(w0 * inv);
    g_M_h[o + t + 256] = __float2half_rn(w1 * inv);
}

extern "C" void kernel_launch(void* const* d_in, const int* in_sizes, int n_in,
                              void* d_out, int out_size) {
    const float* x  = (const float*)d_in[0];
    const float* gm = (const float*)d_in[1];
    float*       y  = (float*)d_out;
    (void)in_sizes; (void)n_in; (void)out_size;

    cudaFuncSetAttribute(split_kernel,    cudaFuncAttributeMaxDynamicSharedMemorySize, SPLIT_SMEM);
    cudaFuncSetAttribute(gram_mma_kernel, cudaFuncAttributeMaxDynamicSharedMemorySize, SMEM_TOT);
    cudaFuncSetAttribute(out_mma_kernel,  cudaFuncAttributeMaxDynamicSharedMemorySize, O_SMEM);

    split_kernel<<<dim3(NDIM / 64, CDIM / 256, BATCH), 256, SPLIT_SMEM>>>(x);
    gram_mma_kernel<<<dim3(10, KSPLIT, BATCH), 256, SMEM_TOT>>>();
    softmax_kernel<<<dim3(CDIM, BATCH), 256>>>(gm);
    out_mma_kernel<<<dim3(NDIM / 128, 4, BATCH), 256, O_SMEM>>>(x, y);
}

// round 8
// speedup vs baseline: 2.5814x; 1.4430x over previous
#include <cuda_runtime.h>
#include <cuda_fp16.h>
#include <cstdint>

#define BATCH 8
#define NDIM  16384
#define CDIM  512
#define KSPLIT 4
#define KSEG  (NDIM / KSPLIT)   // 4096

// Tiled-swizzled operand storage: one 4096B block per (tile, K-stage).
// Block holds 128 rows x 16 halves; unit u = 2*r + h (16B units),
// placed at byte offset ((u ^ ((u>>3)&1)) << 4).
__device__ __half g_XtT_h[(size_t)BATCH * 4 * 1024 * 2048];  // [b][ct][nstage] gram A/B hi
__device__ __half g_XtT_l[(size_t)BATCH * 4 * 1024 * 2048];  // lo
__device__ __half g_XcT_h[(size_t)BATCH * 128 * 32 * 2048];  // [b][nt][cstage] out A hi
__device__ __half g_MT_h [(size_t)BATCH * 4 * 32 * 2048];    // [b][it][cstage] out B hi
__device__ float  g_Epart[(size_t)KSPLIT * BATCH * CDIM * CDIM];

// ---- helpers -------------------------------------------------------------
__device__ __forceinline__ uint32_t s2u(const void* p) {
    uint32_t a;
    asm("{ .reg .u64 t; cvta.to.shared.u64 t, %1; cvt.u32.u64 %0, t; }" : "=r"(a) : "l"(p));
    return a;
}
__device__ __forceinline__ void ldm4(uint32_t* r, uint32_t a) {
    asm volatile("ldmatrix.sync.aligned.m8n8.x4.shared.b16 {%0,%1,%2,%3},[%4];"
                 : "=r"(r[0]), "=r"(r[1]), "=r"(r[2]), "=r"(r[3]) : "r"(a));
}
__device__ __forceinline__ void mma16816(float* d, const uint32_t* a, const uint32_t* b) {
    asm volatile("mma.sync.aligned.m16n8k16.row.col.f32.f16.f16.f32 "
                 "{%0,%1,%2,%3},{%4,%5,%6,%7},{%8,%9},{%0,%1,%2,%3};"
                 : "+f"(d[0]), "+f"(d[1]), "+f"(d[2]), "+f"(d[3])
                 : "r"(a[0]), "r"(a[1]), "r"(a[2]), "r"(a[3]), "r"(b[0]), "r"(b[1]));
}
#define MBI(a, n) asm volatile("mbarrier.init.shared.b64 [%0], %1;" :: "r"(a), "r"((uint32_t)(n)) : "memory")
#define MBA(a)    asm volatile("mbarrier.arrive.shared.b64 _, [%0];" :: "r"(a) : "memory")
#define MBX(a, tx) asm volatile("mbarrier.arrive.expect_tx.shared.b64 _, [%0], %1;" :: "r"(a), "r"((uint32_t)(tx)) : "memory")
#define MBW(a, p) do { \
    asm volatile("{\n\t.reg .pred P;\n\tWL_%=:\n\t" \
        "mbarrier.try_wait.parity.acquire.cta.shared::cta.b64 P, [%0], %1, 0x989680;\n\t" \
        "@P bra.uni WD_%=;\n\tbra.uni WL_%=;\n\tWD_%=:\n\t}" \
        :: "r"(a), "r"((uint32_t)(p)) : "memory"); } while (0)
#define BULK(dst, src, mb) \
    asm volatile("cp.async.bulk.shared::cluster.global.mbarrier::complete_tx::bytes [%0], [%1], %2, [%3];" \
        :: "r"(dst), "l"(src), "r"(4096u), "r"(mb) : "memory")

__device__ __forceinline__ uint32_t swzoff(int r, int h) {
    int u = 2 * r + h;
    return (uint32_t)((u ^ ((u >> 3) & 1)) << 4);
}
__device__ __forceinline__ uint32_t hpack(float a, float b) {
    __half2 H = __halves2half2(__float2half_rn(a), __float2half_rn(b));
    return *reinterpret_cast<uint32_t*>(&H);
}
__device__ __forceinline__ uint32_t lpack(float a, float b) {
    __half ha = __float2half_rn(a), hb = __float2half_rn(b);
    __half2 L = __halves2half2(__float2half_rn(a - __half2float(ha)),
                               __float2half_rn(b - __half2float(hb)));
    return *reinterpret_cast<uint32_t*>(&L);
}

// gram smem: 4 slots x 16KB (AH,AL,BH,BL @ 4KB); barriers at 65536; mirror scratch reuses all
#define G_SLOT 16384
#define G_NSTG 4
#define G_BAR  65536
#define SMEM_G 67584          // >= 128*132*4 mirror scratch
// out smem: 8 slots x 8KB (A,B @ 4KB); barriers at 65536
#define O_SLOT 8192
#define O_NSTG 8
#define O_BAR  65536
#define SMEM_O 65792
#define SPLIT_SMEM (64 * 257 * 4)

// ---------------------------------------------------------------------------
// split: x[b][n][c] -> tiled-swizzled XcT_h, XtT_h/l
// ---------------------------------------------------------------------------
__global__ void __launch_bounds__(256) split_kernel(const float* __restrict__ x) {
    extern __shared__ float sm[];  // [64][257]
    const int n0 = blockIdx.x * 64, c0 = blockIdx.y * 256, b = blockIdx.z;
    const int t = threadIdx.x;
    const float* Xb = x + (size_t)b * NDIM * CDIM;
    #pragma unroll
    for (int r = 0; r < 64; r++) sm[r * 257 + t] = Xb[(size_t)(n0 + r) * CDIM + c0 + t];
    __syncthreads();

    {   // XcT hi: thread -> n-row (t&63), 64-channel chunk (t>>6)
        const int rl = t & 63, chunk = t >> 6;
        const int n = n0 + rl, nt = n >> 7, r = n & 127;
        char* base = (char*)g_XcT_h + ((size_t)(b * 128 + nt) * 32) * 4096;
        #pragma unroll
        for (int q = 0; q < 4; q++) {
            const int s = (c0 >> 4) + chunk * 4 + q;
            const float* src = sm + rl * 257 + chunk * 64 + q * 16;
            uint32_t w[8];
            #pragma unroll
            for (int e = 0; e < 8; e++) w[e] = hpack(src[2 * e], src[2 * e + 1]);
            char* blk = base + (size_t)s * 4096;
            *(uint4*)(blk + swzoff(r, 0)) = make_uint4(w[0], w[1], w[2], w[3]);
            *(uint4*)(blk + swzoff(r, 1)) = make_uint4(w[4], w[5], w[6], w[7]);
        }
    }
    {   // XtT hi+lo: thread -> channel c0+t, 4 n-stages
        const int c = c0 + t, ct = c >> 7, r = c & 127;
        const size_t tb = ((size_t)(b * 4 + ct) * 1024) * 4096;
        char* bh = (char*)g_XtT_h + tb;
        char* bl = (char*)g_XtT_l + tb;
        #pragma unroll
        for (int q = 0; q < 4; q++) {
            const int s = (n0 >> 4) + q;
            uint32_t wh[8], wl[8];
            #pragma unroll
            for (int e = 0; e < 8; e++) {
                float a = sm[(q * 16 + 2 * e) * 257 + t];
                float bvx = sm[(q * 16 + 2 * e + 1) * 257 + t];
                wh[e] = hpack(a, bvx);
                wl[e] = lpack(a, bvx);
            }
            char* kh = bh + (size_t)s * 4096;
            char* kl = bl + (size_t)s * 4096;
            *(uint4*)(kh + swzoff(r, 0)) = make_uint4(wh[0], wh[1], wh[2], wh[3]);
            *(uint4*)(kh + swzoff(r, 1)) = make_uint4(wh[4], wh[5], wh[6], wh[7]);
            *(uint4*)(kl + swzoff(r, 0)) = make_uint4(wl[0], wl[1], wl[2], wl[3]);
            *(uint4*)(kl + swzoff(r, 1)) = make_uint4(wl[4], wl[5], wl[6], wl[7]);
        }
    }
}

// ---------------------------------------------------------------------------
// gram: E = Xt Xt^T (3-pass hi/lo), bulk-copy pipeline, upper tiles + K split
// ---------------------------------------------------------------------------
__global__ void __launch_bounds__(256, 2) gram_mma_kernel() {
    const int IT[10] = {0,0,0,0,1,1,1,2,2,3};
    const int JT[10] = {0,1,2,3,1,2,3,2,3,3};
    const int pi = blockIdx.x, ks = blockIdx.y, b = blockIdx.z;
    const int it = IT[pi], jt = JT[pi];
    const bool same = (it == jt);
    const int i0 = it * 128, j0 = jt * 128;

    extern __shared__ __align__(1024) char smem[];
    const int tid = threadIdx.x, lane = tid & 31;
    const int mo = ((tid >> 5) & 3) * 32, no = (tid >> 7) * 64;
    const uint32_t sbase = s2u(smem);
    const uint32_t FB = sbase + G_BAR, EB = sbase + G_BAR + 32;

    if (tid == 0) {
        #pragma unroll
        for (int k = 0; k < G_NSTG; k++) { MBI(FB + 8 * k, 1); MBI(EB + 8 * k, 256); }
    }
    __syncthreads();

    const char* pAh = (char*)g_XtT_h + ((size_t)(b * 4 + it) * 1024 + ks * 256) * 4096;
    const char* pAl = (char*)g_XtT_l + ((size_t)(b * 4 + it) * 1024 + ks * 256) * 4096;
    const char* pBh = (char*)g_XtT_h + ((size_t)(b * 4 + jt) * 1024 + ks * 256) * 4096;
    const char* pBl = (char*)g_XtT_l + ((size_t)(b * 4 + jt) * 1024 + ks * 256) * 4096;
    const uint32_t rb_off = same ? 0u : 8192u;
    const uint32_t tx = same ? 8192u : 16384u;
    const int nst = KSEG / 16;  // 256

    #define G_ISSUE(j) do {                                            \
        uint32_t dst = sbase + (uint32_t)((j) & 3) * G_SLOT;           \
        uint32_t mb = FB + ((j) & 3) * 8;                              \
        MBX(mb, tx);                                                   \
        BULK(dst,        pAh + (size_t)(j) * 4096, mb);                \
        BULK(dst + 4096, pAl + (size_t)(j) * 4096, mb);                \
        if (!same) {                                                   \
            BULK(dst + 8192,  pBh + (size_t)(j) * 4096, mb);           \
            BULK(dst + 12288, pBl + (size_t)(j) * 4096, mb);           \
        }                                                              \
    } while (0)

    if (tid == 0) { G_ISSUE(0); G_ISSUE(1); G_ISSUE(2); }

    const uint32_t swzA = swzoff(lane & 15, lane >> 4);
    const uint32_t swzB = swzoff((lane & 7) + ((lane >> 4) & 1) * 8, (lane >> 3) & 1);

    float acc[2][8][4];
    #pragma unroll
    for (int i = 0; i < 2; i++)
        #pragma unroll
        for (int j = 0; j < 8; j++)
            #pragma unroll
            for (int q = 0; q < 4; q++) acc[i][j][q] = 0.0f;

    for (int s = 0; s < nst; s++) {
        const int slot = s & 3;
        MBW(FB + slot * 8, (s >> 2) & 1);

        const uint32_t bb = sbase + (uint32_t)slot * G_SLOT;
        const uint32_t ra_h = bb, ra_l = bb + 4096;
        const uint32_t rbh = bb + rb_off, rbl = bb + rb_off + 4096;

        uint32_t ah[2][4], al[2][4];
        #pragma unroll
        for (int mi = 0; mi < 2; mi++) {
            uint32_t ro = (uint32_t)(mo + mi * 16) * 32;
            ldm4(ah[mi], ra_h + ro + swzA);
            ldm4(al[mi], ra_l + ro + swzA);
        }
        uint32_t bhp[2][4], blp[2][4];
        ldm4(bhp[0], rbh + (uint32_t)no * 32 + swzB);
        ldm4(blp[0], rbl + (uint32_t)no * 32 + swzB);
        #pragma unroll
        for (int p = 0; p < 4; p++) {
            if (p < 3) {
                uint32_t ro = (uint32_t)(no + (p + 1) * 16) * 32;
                ldm4(bhp[(p + 1) & 1], rbh + ro + swzB);
                ldm4(blp[(p + 1) & 1], rbl + ro + swzB);
            }
            uint32_t* ch = bhp[p & 1];
            uint32_t* cl = blp[p & 1];
            #pragma unroll
            for (int hf = 0; hf < 2; hf++) {
                int ni = p * 2 + hf;
                #pragma unroll
                for (int mi = 0; mi < 2; mi++) {
                    mma16816(acc[mi][ni], ah[mi], ch + hf * 2);
                    mma16816(acc[mi][ni], ah[mi], cl + hf * 2);
                    mma16816(acc[mi][ni], al[mi], ch + hf * 2);
                }
            }
        }
        MBA(EB + slot * 8);
        if (tid == 0) {
            int j = s + 3;
            if (j < nst) {
                if (j >= 4) MBW(EB + (j & 3) * 8, ((j >> 2) - 1) & 1);
                G_ISSUE(j);
            }
        }
    }
    #undef G_ISSUE

    // epilogue: Epart + mirror
    const int er = lane >> 2, ec = (lane & 3) * 2;
    float* Ep = g_Epart + (((size_t)ks * BATCH + b) * CDIM + i0) * CDIM + j0;
    #pragma unroll
    for (int mi = 0; mi < 2; mi++)
        #pragma unroll
        for (int ni = 0; ni < 8; ni++) {
            int r0 = mo + mi * 16 + er;
            int c  = no + ni * 8 + ec;
            *(float2*)(Ep + (size_t)r0 * CDIM + c)       = make_float2(acc[mi][ni][0], acc[mi][ni][1]);
            *(float2*)(Ep + (size_t)(r0 + 8) * CDIM + c) = make_float2(acc[mi][ni][2], acc[mi][ni][3]);
        }

    if (!same) {
        float* ts = (float*)smem;  // stride 132, reuses pipeline smem (stages all consumed)
        __syncthreads();
        #pragma unroll
        for (int mi = 0; mi < 2; mi++)
            #pragma unroll
            for (int ni = 0; ni < 8; ni++) {
                int r0 = mo + mi * 16 + er, c = no + ni * 8 + ec;
                ts[r0 * 132 + c]           = acc[mi][ni][0];
                ts[r0 * 132 + c + 1]       = acc[mi][ni][1];
                ts[(r0 + 8) * 132 + c]     = acc[mi][ni][2];
                ts[(r0 + 8) * 132 + c + 1] = acc[mi][ni][3];
            }
        __syncthreads();
        float* Em = g_Epart + (((size_t)ks * BATCH + b) * CDIM + j0) * CDIM + i0;
        const int j = tid >> 1, hf = tid & 1;
        float* dst = Em + (size_t)j * CDIM + hf * 64;
        #pragma unroll
        for (int w = 0; w < 16; w++) {
            float4 v = make_float4(ts[(hf * 64 + 4 * w) * 132 + j],
                                   ts[(hf * 64 + 4 * w + 1) * 132 + j],
                                   ts[(hf * 64 + 4 * w + 2) * 132 + j],
                                   ts[(hf * 64 + 4 * w + 3) * 132 + j]);
            *(float4*)(dst + 4 * w) = v;
        }
    }
}

// ---------------------------------------------------------------------------
// out: Y = Xc_h * M'^T (single pass) + x,  bulk pipeline
// ---------------------------------------------------------------------------
__global__ void __launch_bounds__(256, 2) out_mma_kernel(const float* __restrict__ x,
                                                         float* __restrict__ y) {
    extern __shared__ __align__(1024) char smem[];
    const int nt = blockIdx.x, itile = blockIdx.y, b = blockIdx.z;
    const int n0 = nt * 128, i0 = itile * 128;
    const int tid = threadIdx.x, lane = tid & 31;
    const int mo = ((tid >> 5) & 3) * 32, no = (tid >> 7) * 64;
    const uint32_t sbase = s2u(smem);
    const uint32_t FB = sbase + O_BAR, EB = sbase + O_BAR + 64;

    if (tid == 0) {
        #pragma unroll
        for (int k = 0; k < O_NSTG; k++) { MBI(FB + 8 * k, 1); MBI(EB + 8 * k, 256); }
    }
    __syncthreads();

    const char* pA = (char*)g_XcT_h + ((size_t)(b * 128 + nt) * 32) * 4096;
    const char* pB = (char*)g_MT_h + ((size_t)(b * 4 + itile) * 32) * 4096;
    const int nst = CDIM / 16;  // 32

    #define O_ISSUE(j) do {                                            \
        uint32_t dst = sbase + (uint32_t)((j) & 7) * O_SLOT;           \
        uint32_t mb = FB + ((j) & 7) * 8;                              \
        MBX(mb, 8192u);                                                \
        BULK(dst,        pA + (size_t)(j) * 4096, mb);                 \
        BULK(dst + 4096, pB + (size_t)(j) * 4096, mb);                 \
    } while (0)

    if (tid == 0) {
        #pragma unroll
        for (int p = 0; p < O_NSTG - 1; p++) O_ISSUE(p);
    }

    const uint32_t swzA = swzoff(lane & 15, lane >> 4);
    const uint32_t swzB = swzoff((lane & 7) + ((lane >> 4) & 1) * 8, (lane >> 3) & 1);

    float acc[2][8][4];
    #pragma unroll
    for (int i = 0; i < 2; i++)
        #pragma unroll
        for (int j = 0; j < 8; j++)
            #pragma unroll
            for (int q = 0; q < 4; q++) acc[i][j][q] = 0.0f;

    for (int s = 0; s < nst; s++) {
        const int slot = s & 7;
        MBW(FB + slot * 8, (s >> 3) & 1);

        const uint32_t bb = sbase + (uint32_t)slot * O_SLOT;
        uint32_t ah[2][4];
        #pragma unroll
        for (int mi = 0; mi < 2; mi++)
            ldm4(ah[mi], bb + (uint32_t)(mo + mi * 16) * 32 + swzA);
        uint32_t bhp[2][4];
        ldm4(bhp[0], bb + 4096 + (uint32_t)no * 32 + swzB);
        #pragma unroll
        for (int p = 0; p < 4; p++) {
            if (p < 3)
                ldm4(bhp[(p + 1) & 1], bb + 4096 + (uint32_t)(no + (p + 1) * 16) * 32 + swzB);
            uint32_t* ch = bhp[p & 1];
            #pragma unroll
            for (int hf = 0; hf < 2; hf++) {
                int ni = p * 2 + hf;
                #pragma unroll
                for (int mi = 0; mi < 2; mi++)
                    mma16816(acc[mi][ni], ah[mi], ch + hf * 2);
            }
        }
        MBA(EB + slot * 8);
        if (tid == 0) {
            int j = s + O_NSTG - 1;
            if (j < nst) {
                if (j >= O_NSTG) MBW(EB + (j & 7) * 8, ((j >> 3) - 1) & 1);
                O_ISSUE(j);
            }
        }
    }
    #undef O_ISSUE

    // epilogue: add exact fp32 residual x[n][i]
    const float* xr = x + ((size_t)b * NDIM + n0) * CDIM + i0;
    float* yr = y + ((size_t)b * NDIM + n0) * CDIM + i0;
    const int er = lane >> 2, ec = (lane & 3) * 2;
    #pragma unroll
    for (int mi = 0; mi < 2; mi++)
        #pragma unroll
        for (int ni = 0; ni < 8; ni++) {
            int r0 = mo + mi * 16 + er;
            int c  = no + ni * 8 + ec;
            float2 x0 = *(const float2*)(xr + (size_t)r0 * CDIM + c);
            float2 x1 = *(const float2*)(xr + (size_t)(r0 + 8) * CDIM + c);
            *(float2*)(yr + (size_t)r0 * CDIM + c) =
                make_float2(acc[mi][ni][0] + x0.x, acc[mi][ni][1] + x0.y);
            *(float2*)(yr + (size_t)(r0 + 8) * CDIM + c) =
                make_float2(acc[mi][ni][2] + x1.x, acc[mi][ni][3] + x1.y);
        }
}

// ---------------------------------------------------------------------------
// softmax(-E) over summed K-partials; writes tiled-swizzled M' = gamma*att
// ---------------------------------------------------------------------------
__global__ void __launch_bounds__(256) softmax_kernel(const float* __restrict__ gp) {
    const int i = blockIdx.x, b = blockIdx.y;
    __shared__ float sm[256];
    __shared__ __half hrow[512];
    const int t = threadIdx.x;
    float v0 = 0.0f, v1 = 0.0f;
    #pragma unroll
    for (int ks = 0; ks < KSPLIT; ks++) {
        const float* e = g_Epart + (((size_t)ks * BATCH + b) * CDIM + i) * CDIM;
        v0 += e[t];
        v1 += e[t + 256];
    }
    sm[t] = fminf(v0, v1);
    __syncthreads();
    for (int s = 128; s > 0; s >>= 1) { if (t < s) sm[t] = fminf(sm[t], sm[t + s]); __syncthreads(); }
    float mn = sm[0];
    __syncthreads();
    float w0 = __expf(mn - v0), w1 = __expf(mn - v1);
    sm[t] = w0 + w1;
    __syncthreads();
    for (int s = 128; s > 0; s >>= 1) { if (t < s) sm[t] += sm[t + s]; __syncthreads(); }
    float inv = gp[0] / sm[0];
    hrow[t]       = __float2half_rn(w0 * inv);
    hrow[t + 256] = __float2half_rn(w1 * inv);
    __syncthreads();
    if (t < 64) {
        const int s = t >> 1, h = t & 1;
        const __half* src = hrow + s * 16 + h * 8;
        uint32_t w[4];
        #pragma unroll
        for (int e = 0; e < 4; e++) w[e] = *(const uint32_t*)(src + 2 * e);
        char* blk = (char*)g_MT_h + ((size_t)(b * 4 + (i >> 7)) * 32 + s) * 4096;
        *(uint4*)(blk + swzoff(i & 127, h)) = make_uint4(w[0], w[1], w[2], w[3]);
    }
}

extern "C" void kernel_launch(void* const* d_in, const int* in_sizes, int n_in,
                              void* d_out, int out_size) {
    const float* x  = (const float*)d_in[0];
    const float* gm = (const float*)d_in[1];
    float*       y  = (float*)d_out;
    (void)in_sizes; (void)n_in; (void)out_size;

    cudaFuncSetAttribute(split_kernel,    cudaFuncAttributeMaxDynamicSharedMemorySize, SPLIT_SMEM);
    cudaFuncSetAttribute(gram_mma_kernel, cudaFuncAttributeMaxDynamicSharedMemorySize, SMEM_G);
    cudaFuncSetAttribute(out_mma_kernel,  cudaFuncAttributeMaxDynamicSharedMemorySize, SMEM_O);

    split_kernel<<<dim3(NDIM / 64, CDIM / 256, BATCH), 256, SPLIT_SMEM>>>(x);
    gram_mma_kernel<<<dim3(10, KSPLIT, BATCH), 256, SMEM_G>>>();
    softmax_kernel<<<dim3(CDIM, BATCH), 256>>>(gm);
    out_mma_kernel<<<dim3(NDIM / 128, 4, BATCH), 256, SMEM_O>>>(x, y);
}